// round 14
// baseline (speedup 1.0000x reference)
#include <cuda_runtime.h>
#include <cuda_bf16.h>

// Problem constants (B=8, T=4096, C=512)
#define B_DIM  8
#define T_DIM  4096
#define C_DIM  512
#define NCHUNK 32                  // chunks along T
#define CHUNK  128                 // timesteps per chunk (dense 256 KB x slab)
#define SEGL   64                  // timesteps per thread-segment (2 segs/chunk)
#define NPAIR  256                 // channel pairs (2 ch per thread)
#define UNR    8
#define XS2    (C_DIM / 2)         // float2 stride per timestep in x
#define OS4    (C_DIM * 2 / 4)     // float4 stride per timestep in out

// scratch (graph-safe __device__ globals)
__device__ __align__(16) float g_F0[B_DIM * NCHUNK * C_DIM * 2];  // seg0 finals, 1 MB
__device__ __align__(16) float g_CF[B_DIM * NCHUNK * C_DIM * 2];  // chunk aggregates, 1 MB
__device__ __align__(16) float g_CS[B_DIM * NCHUNK * C_DIM * 2];  // chunk starts, 1 MB

__device__ __forceinline__ void step2(float2& hr, float2& hi,
                                      const float2 Ar, const float2 Ai,
                                      const float2 xv) {
    float2 nr, ni;
    nr.x = fmaf(hr.x, Ar.x, fmaf(-hi.x, Ai.x, xv.x));
    ni.x = fmaf(hr.x, Ai.x, hi.x * Ar.x);
    nr.y = fmaf(hr.y, Ar.y, fmaf(-hi.y, Ai.y, xv.y));
    ni.y = fmaf(hr.y, Ai.y, hi.y * Ar.y);
    hr = nr; hi = ni;
}

// z <- z^(2^k)
__device__ __forceinline__ void cpow2k(float& r, float& i, int k) {
    for (int s = 0; s < k; s++) {
        float nr = r * r - i * i;
        float ni = 2.f * r * i;
        r = nr; i = ni;
    }
}

// ---------------- K1: dense zero-start chunk scans ----------------
__global__ __launch_bounds__(512)
void k1_scan(const float* __restrict__ x,
             const float* __restrict__ Ar_g,
             const float* __restrict__ Ai_g) {
    __shared__ float4 s_f0[NPAIR];

    const int pair  = threadIdx.x & 255;
    const int seg   = threadIdx.x >> 8;          // 0 or 1
    const int b     = blockIdx.x >> 5;
    const int chunk = blockIdx.x & 31;
    const int c0    = pair * 2;
    const int t0    = chunk * CHUNK + seg * SEGL;

    const float2 Ar = *reinterpret_cast<const float2*>(Ar_g + c0);
    const float2 Ai = *reinterpret_cast<const float2*>(Ai_g + c0);

    const float2* xq = reinterpret_cast<const float2*>(x)
                       + ((size_t)(b * T_DIM + t0) * C_DIM + c0) / 2;

    float2 hr = make_float2(0.f, 0.f), hi = make_float2(0.f, 0.f);
    #pragma unroll 1
    for (int j = 0; j < SEGL; j += UNR) {
        float2 xv[UNR];
        #pragma unroll
        for (int k = 0; k < UNR; k++) xv[k] = xq[(size_t)(j + k) * XS2];
        #pragma unroll
        for (int k = 0; k < UNR; k++) step2(hr, hi, Ar, Ai, xv[k]);
    }

    const size_t so = ((size_t)(b * NCHUNK + chunk) * C_DIM + c0) * 2;
    if (seg == 0) {
        float4 f = make_float4(hr.x, hi.x, hr.y, hi.y);
        s_f0[pair] = f;
        *reinterpret_cast<float4*>(g_F0 + so) = f;
    }
    __syncthreads();
    if (seg == 1) {
        float4 f0 = s_f0[pair];
        // per-channel A^64
        float pxr = Ar.x, pxi = Ai.x; cpow2k(pxr, pxi, 6);
        float pyr = Ar.y, pyi = Ai.y; cpow2k(pyr, pyi, 6);
        // CF = A^64 * f0 + f1
        float4 cf;
        cf.x = fmaf(pxr, f0.x, fmaf(-pxi, f0.y, hr.x));
        cf.y = fmaf(pxr, f0.y, fmaf( pxi, f0.x, hi.x));
        cf.z = fmaf(pyr, f0.z, fmaf(-pyi, f0.w, hr.y));
        cf.w = fmaf(pyr, f0.w, fmaf( pyi, f0.z, hi.y));
        *reinterpret_cast<float4*>(g_CF + so) = cf;
    }
}

// ---------------- K2: serial prefix over 32 chunks per (b, c) ----------------
__global__ __launch_bounds__(512)
void k2_combine(const float* __restrict__ Ar_g,
                const float* __restrict__ Ai_g,
                const float* __restrict__ h0r_g,
                const float* __restrict__ h0i_g) {
    const int b = blockIdx.x;       // 8 blocks
    const int c = threadIdx.x;      // 512 threads

    float pr = Ar_g[c], pi = Ai_g[c];
    cpow2k(pr, pi, 7);              // A^128

    float cr = h0r_g[(size_t)b * C_DIM + c];
    float ci = h0i_g[(size_t)b * C_DIM + c];
    #pragma unroll 4
    for (int k = 0; k < NCHUNK; k++) {
        const size_t o = ((size_t)(b * NCHUNK + k) * C_DIM + c) * 2;
        *reinterpret_cast<float2*>(g_CS + o) = make_float2(cr, ci);
        float2 cf = *reinterpret_cast<const float2*>(g_CF + o);
        float nr = fmaf(pr, cr, fmaf(-pi, ci, cf.x));
        float ni = fmaf(pr, ci, fmaf( pi, cr, cf.y));
        cr = nr; ci = ni;
    }
}

// ---------------- K3: dense replay + output ----------------
__global__ __launch_bounds__(512)
void k3_replay(const float* __restrict__ x,
               const float* __restrict__ Ar_g,
               const float* __restrict__ Ai_g,
               float* __restrict__ out) {
    const int pair  = threadIdx.x & 255;
    const int seg   = threadIdx.x >> 8;
    const int b     = blockIdx.x >> 5;
    const int chunk = blockIdx.x & 31;
    const int c0    = pair * 2;
    const int t0    = chunk * CHUNK + seg * SEGL;

    const float2 Ar = *reinterpret_cast<const float2*>(Ar_g + c0);
    const float2 Ai = *reinterpret_cast<const float2*>(Ai_g + c0);

    const size_t so = ((size_t)(b * NCHUNK + chunk) * C_DIM + c0) * 2;
    float4 cs = *reinterpret_cast<const float4*>(g_CS + so);
    float2 hr = make_float2(cs.x, cs.z);
    float2 hi = make_float2(cs.y, cs.w);
    if (seg == 1) {
        float4 f0 = *reinterpret_cast<const float4*>(g_F0 + so);
        float pxr = Ar.x, pxi = Ai.x; cpow2k(pxr, pxi, 6);
        float pyr = Ar.y, pyi = Ai.y; cpow2k(pyr, pyi, 6);
        // seg1 start = A^64 * chunk_start + F0
        hr.x = fmaf(pxr, cs.x, fmaf(-pxi, cs.y, f0.x));
        hi.x = fmaf(pxr, cs.y, fmaf( pxi, cs.x, f0.y));
        hr.y = fmaf(pyr, cs.z, fmaf(-pyi, cs.w, f0.z));
        hi.y = fmaf(pyr, cs.w, fmaf( pyi, cs.z, f0.w));
    }

    const float2* xq = reinterpret_cast<const float2*>(x)
                       + ((size_t)(b * T_DIM + t0) * C_DIM + c0) / 2;
    float4* op = reinterpret_cast<float4*>(out)
                 + ((size_t)(b * T_DIM + t0) * C_DIM + c0) * 2 / 4;

    #pragma unroll 1
    for (int j = 0; j < SEGL; j += UNR) {
        float2 xv[UNR];
        #pragma unroll
        for (int k = 0; k < UNR; k++)
            xv[k] = __ldcs(xq + (size_t)(j + k) * XS2);      // read-once
        #pragma unroll
        for (int k = 0; k < UNR; k++) {
            step2(hr, hi, Ar, Ai, xv[k]);
            __stcs(op + (size_t)(j + k) * OS4,
                   make_float4(hr.x, hi.x, hr.y, hi.y));     // streaming store
        }
    }
}

extern "C" void kernel_launch(void* const* d_in, const int* in_sizes, int n_in,
                              void* d_out, int out_size) {
    const float* x   = (const float*)d_in[0];   // (B, T, C)
    const float* Ar  = (const float*)d_in[1];   // (C,)
    const float* Ai  = (const float*)d_in[2];   // (C,)
    const float* h0r = (const float*)d_in[3];   // (B, C)
    const float* h0i = (const float*)d_in[4];   // (B, C)
    float* out = (float*)d_out;                 // (B, T, C, 2)

    dim3 grid(B_DIM * NCHUNK);                  // 256 dense blocks
    k1_scan<<<grid, 512>>>(x, Ar, Ai);
    k2_combine<<<B_DIM, 512>>>(Ar, Ai, h0r, h0i);
    k3_replay<<<grid, 512>>>(x, Ar, Ai, out);
}